// round 2
// baseline (speedup 1.0000x reference)
#include <cuda_runtime.h>

#define TPB 256
#define ITEMS 8
#define TILE (TPB * ITEMS)            // 2048
#define MAX_BOND (1 << 22)            // 4M bonds max
#define MAX_ATOM (1 << 20)            // 1M atoms max
#define MAX_BTILES (MAX_BOND / TILE)  // 2048
#define MAX_ATILES (MAX_ATOM / TILE)  // 512
#define CUTOFF 0.8f

// ---------------- scratch (static device globals; no allocations) ----------
__device__ int g_kept[MAX_BOND];      // original bond ids of surviving bonds
__device__ int g_deg[MAX_ATOM];       // kept-bond degree per atom
__device__ int g_bondOff[MAX_ATOM];   // CSR start into g_kept per atom
__device__ int g_triStart[MAX_ATOM];  // exclusive prefix of d*(d-1)
__device__ int g_btCnt[MAX_BTILES];
__device__ int g_btOff[MAX_BTILES];
__device__ unsigned long long g_atPack[MAX_ATILES];     // (tri<<32)|deg tile sums
__device__ unsigned long long g_atPackOff[MAX_ATILES];  // exclusive tile offsets
__device__ int g_M;                   // total kept bonds
__device__ int g_T;                   // total triples
__device__ int g_nAtom;               // sum(n_atoms)
__device__ int g_bound[260];          // struct boundaries (exclusive scan of n_atoms)

// ---------------- scan helpers --------------------------------------------
template <typename T>
__device__ __forceinline__ T warpIncl(T v) {
#pragma unroll
    for (int d = 1; d < 32; d <<= 1) {
        T n = __shfl_up_sync(0xffffffffu, v, d);
        if ((threadIdx.x & 31) >= d) v += n;
    }
    return v;
}

// Block-wide exclusive scan. smem must have >= 33 elements. Safe to call in a
// loop (trailing barrier). total (optional) receives the block sum.
template <typename T>
__device__ __forceinline__ T blockExcl(T v, T* smem, T* total) {
    int lane = threadIdx.x & 31, w = threadIdx.x >> 5, nw = blockDim.x >> 5;
    T inc = warpIncl(v);
    if (lane == 31) smem[w] = inc;
    __syncthreads();
    if (w == 0) {
        T x = (lane < nw) ? smem[lane] : (T)0;
        T xi = warpIncl(x);
        if (lane < nw) smem[lane] = xi - x;
        if (lane == nw - 1) smem[32] = xi;
    }
    __syncthreads();
    T res = inc - v + smem[w];
    T tot = smem[32];
    __syncthreads();
    if (total) *total = tot;
    return res;
}

// ---------------- kernels --------------------------------------------------
__global__ void k_zero_deg() {
    int i = blockIdx.x * blockDim.x + threadIdx.x;
    if (i < MAX_ATOM) g_deg[i] = 0;
}

// Per-tile kept count + run-aggregated degree histogram.
__global__ void k_filter(const int* __restrict__ src, const float* __restrict__ len,
                         int n_bond) {
    __shared__ int sm[33];
    int base = blockIdx.x * TILE + threadIdx.x * ITEMS;
    int cnt = 0;
    int curA = -1, curC = 0;
    if (base + ITEMS <= n_bond) {
        float4 l0 = *(const float4*)(len + base);
        float4 l1 = *(const float4*)(len + base + 4);
        int4 s0 = *(const int4*)(src + base);
        int4 s1 = *(const int4*)(src + base + 4);
        float lv[8] = {l0.x, l0.y, l0.z, l0.w, l1.x, l1.y, l1.z, l1.w};
        int sv[8] = {s0.x, s0.y, s0.z, s0.w, s1.x, s1.y, s1.z, s1.w};
#pragma unroll
        for (int i = 0; i < 8; i++) {
            if (lv[i] <= CUTOFF) {
                cnt++;
                int a = sv[i];
                if (a == curA) curC++;
                else { if (curC) atomicAdd(&g_deg[curA], curC); curA = a; curC = 1; }
            }
        }
    } else {
        for (int i = 0; i < ITEMS; i++) {
            int b = base + i;
            if (b < n_bond && len[b] <= CUTOFF) {
                cnt++;
                int a = src[b];
                if (a == curA) curC++;
                else { if (curC) atomicAdd(&g_deg[curA], curC); curA = a; curC = 1; }
            }
        }
    }
    if (curC) atomicAdd(&g_deg[curA], curC);
    int tot;
    blockExcl<int>(cnt, sm, &tot);
    if (threadIdx.x == 0) g_btCnt[blockIdx.x] = tot;
}

// Single block: scan bond-tile counts; also scan n_atoms for struct bounds.
__global__ void k_scan_bt(int nbt, const int* __restrict__ n_atoms, int n_struct) {
    __shared__ int sm[33];
    int carry = 0;
    for (int base = 0; base < nbt; base += blockDim.x) {
        int i = base + threadIdx.x;
        int v = (i < nbt) ? g_btCnt[i] : 0;
        int tot;
        int e = blockExcl<int>(v, sm, &tot);
        if (i < nbt) g_btOff[i] = carry + e;
        carry += tot;
    }
    if (threadIdx.x == 0) {
        g_M = carry;
        int ns = n_struct < 256 ? n_struct : 256;
        int acc = 0;
        for (int s = 0; s < ns; s++) { g_bound[s] = acc; acc += n_atoms[s]; }
        g_bound[ns] = acc;
        g_nAtom = acc;
    }
}

// Order-preserving scatter of kept bond ids.
__global__ void k_scatter(const float* __restrict__ len, int n_bond) {
    __shared__ int sm[33];
    int base = blockIdx.x * TILE + threadIdx.x * ITEMS;
    int flags[ITEMS];
    int cnt = 0;
    if (base + ITEMS <= n_bond) {
        float4 l0 = *(const float4*)(len + base);
        float4 l1 = *(const float4*)(len + base + 4);
        float lv[8] = {l0.x, l0.y, l0.z, l0.w, l1.x, l1.y, l1.z, l1.w};
#pragma unroll
        for (int i = 0; i < 8; i++) { flags[i] = (lv[i] <= CUTOFF); cnt += flags[i]; }
    } else {
        for (int i = 0; i < ITEMS; i++) {
            int b = base + i;
            flags[i] = (b < n_bond && len[b] <= CUTOFF);
            cnt += flags[i];
        }
    }
    int e = blockExcl<int>(cnt, sm, (int*)nullptr);
    int pos = g_btOff[blockIdx.x] + e;
#pragma unroll
    for (int i = 0; i < ITEMS; i++)
        if (flags[i]) g_kept[pos++] = base + i;
}

// Per-atom-tile packed (deg, tri) sums.
__global__ void k_atile() {
    __shared__ unsigned long long sm[33];
    int nA = g_nAtom;
    int base = blockIdx.x * TILE + threadIdx.x * ITEMS;
    unsigned long long acc = 0;
#pragma unroll
    for (int i = 0; i < ITEMS; i++) {
        int a = base + i;
        int d = (a < nA) ? g_deg[a] : 0;
        acc += ((unsigned long long)(unsigned)(d * (d - 1)) << 32) | (unsigned)d;
    }
    unsigned long long tot;
    blockExcl<unsigned long long>(acc, sm, &tot);
    if (threadIdx.x == 0) g_atPack[blockIdx.x] = tot;
}

__global__ void k_scan_at() {
    __shared__ unsigned long long sm[33];
    int nA = g_nAtom;
    int nt = (nA + TILE - 1) / TILE;
    unsigned long long carry = 0;
    for (int base = 0; base < nt; base += blockDim.x) {
        int i = base + threadIdx.x;
        unsigned long long v = (i < nt) ? g_atPack[i] : 0ull;
        unsigned long long tot;
        unsigned long long e = blockExcl<unsigned long long>(v, sm, &tot);
        if (i < nt) g_atPackOff[i] = carry + e;
        carry += tot;
    }
    if (threadIdx.x == 0) g_T = (int)(carry >> 32);
}

// Per-atom CSR offsets + triple starts + n_triple_i output section (FLOAT out).
__global__ void k_awrite(float* __restrict__ out, int out_size, int n_bond, int n_struct) {
    __shared__ unsigned long long sm[33];
    int nA = g_nAtom;
    int base = blockIdx.x * TILE + threadIdx.x * ITEMS;
    int dArr[ITEMS];
    unsigned long long acc = 0;
#pragma unroll
    for (int i = 0; i < ITEMS; i++) {
        int a = base + i;
        int d = (a < nA) ? g_deg[a] : 0;
        dArr[i] = d;
        acc += ((unsigned long long)(unsigned)(d * (d - 1)) << 32) | (unsigned)d;
    }
    unsigned long long e = blockExcl<unsigned long long>(acc, sm, (unsigned long long*)nullptr);
    unsigned long long run =
        ((blockIdx.x * TILE < nA) ? g_atPackOff[blockIdx.x] : 0ull) + e;
    int offTi = out_size - n_struct - nA;
#pragma unroll
    for (int i = 0; i < ITEMS; i++) {
        int a = base + i;
        if (a < nA) {
            int d = dArr[i];
            g_bondOff[a] = (int)(run & 0xffffffffull);
            g_triStart[a] = (int)(run >> 32);
            out[offTi + a] = (float)(d * (d - 1));
            run += ((unsigned long long)(unsigned)(d * (d - 1)) << 32) | (unsigned)d;
        }
    }
}

// n_triple_s per structure (difference of exclusive triple prefix at bounds).
__global__ void k_struct(float* __restrict__ out, int out_size, int n_struct) {
    int s = blockIdx.x * blockDim.x + threadIdx.x;
    if (s < n_struct) {
        int nA = g_nAtom;
        int lo = g_bound[s], hi = g_bound[s + 1];
        int vlo = (lo >= nA) ? g_T : g_triStart[lo];
        int vhi = (hi >= nA) ? g_T : g_triStart[hi];
        out[out_size - n_struct + s] = (float)(vhi - vlo);
    }
}

// n_triple_ij per ORIGINAL bond (FLOAT out).
__global__ void k_tij(const int* __restrict__ src, const float* __restrict__ len,
                      int n_bond, float* __restrict__ out, int out_size, int n_struct) {
    int b = blockIdx.x * blockDim.x + threadIdx.x;
    if (b < n_bond) {
        int v = 0;
        if (len[b] <= CUTOFF) v = g_deg[src[b]] - 1;
        out[out_size - n_struct - g_nAtom - n_bond + b] = (float)v;
    }
}

// One thread per kept bond: emit its (d-1) ordered partner pairs as float2.
__global__ void k_pairs(const int* __restrict__ src, float* __restrict__ out) {
    int r = blockIdx.x * blockDim.x + threadIdx.x;
    if (r >= g_M) return;
    int b = g_kept[r];
    int a = src[b];
    int off = g_bondOff[a];
    int d = g_deg[a];
    int j = r - off;
    int base = g_triStart[a] + j * (d - 1);
    float2* o = (float2*)out;
    float2 v;
    v.x = (float)b;
    for (int kp = 0; kp < d - 1; kp++) {
        int k = kp + (kp >= j);
        v.y = (float)g_kept[off + k];
        o[base + kp] = v;
    }
}

// ---------------- launch ----------------------------------------------------
extern "C" void kernel_launch(void* const* d_in, const int* in_sizes, int n_in,
                              void* d_out, int out_size) {
    const int* src = (const int*)d_in[0];
    const float* len = (const float*)d_in[1];
    const int* n_atoms = (const int*)d_in[2];
    int n_bond = in_sizes[0];
    int n_struct = in_sizes[2];
    float* out = (float*)d_out;

    int nbt = (n_bond + TILE - 1) / TILE;
    int nbb = (n_bond + TPB - 1) / TPB;

    k_zero_deg<<<(MAX_ATOM + 255) / 256, 256>>>();
    k_filter<<<nbt, TPB>>>(src, len, n_bond);
    k_scan_bt<<<1, 1024>>>(nbt, n_atoms, n_struct);
    k_scatter<<<nbt, TPB>>>(len, n_bond);
    k_atile<<<MAX_ATILES, TPB>>>();
    k_scan_at<<<1, 1024>>>();
    k_awrite<<<MAX_ATILES, TPB>>>(out, out_size, n_bond, n_struct);
    k_struct<<<1, 256>>>(out, out_size, n_struct);
    k_tij<<<nbb, TPB>>>(src, len, n_bond, out, out_size, n_struct);
    k_pairs<<<nbb, TPB>>>(src, out);
}

// round 3
// speedup vs baseline: 1.2897x; 1.2897x over previous
#include <cuda_runtime.h>

#define TPB 256
#define ITEMS 8
#define TILE (TPB * ITEMS)            // 2048
#define MAX_BOND (1 << 22)            // 4M bonds max
#define MAX_ATOM (1 << 20)            // 1M atoms max
#define MAX_BTILES (MAX_BOND / TILE)  // 2048
#define MAX_ATILES (MAX_ATOM / TILE)  // 512
#define CUTOFF 0.8f
#define PITEMS 8                      // triples per thread in pairs kernel
#define PAIR_BLOCKS 2048

// ---------------- scratch (static device globals; no allocations) ----------
__device__ int g_kept[MAX_BOND];      // original bond ids of surviving bonds
__device__ int g_deg[MAX_ATOM];       // kept-bond degree per atom
__device__ int2 g_ab[MAX_ATOM];       // {bondOff, deg} per atom
__device__ int g_triStart[MAX_ATOM];  // exclusive prefix of d*(d-1)
__device__ unsigned long long g_mask[MAX_BOND / 64];  // keep-flag bitmask
__device__ int g_btCnt[MAX_BTILES];
__device__ int g_btOff[MAX_BTILES];
__device__ unsigned long long g_atPack[MAX_ATILES];     // (tri<<32)|deg tile sums
__device__ unsigned long long g_atPackOff[MAX_ATILES];  // exclusive tile offsets
__device__ int g_M;                   // total kept bonds
__device__ int g_T;                   // total triples
__device__ int g_nAtom;               // sum(n_atoms)
__device__ int g_bound[260];          // struct boundaries

// ---------------- scan helpers --------------------------------------------
template <typename T>
__device__ __forceinline__ T warpIncl(T v) {
#pragma unroll
    for (int d = 1; d < 32; d <<= 1) {
        T n = __shfl_up_sync(0xffffffffu, v, d);
        if ((threadIdx.x & 31) >= d) v += n;
    }
    return v;
}

template <typename T>
__device__ __forceinline__ T blockExcl(T v, T* smem, T* total) {
    int lane = threadIdx.x & 31, w = threadIdx.x >> 5, nw = blockDim.x >> 5;
    T inc = warpIncl(v);
    if (lane == 31) smem[w] = inc;
    __syncthreads();
    if (w == 0) {
        T x = (lane < nw) ? smem[lane] : (T)0;
        T xi = warpIncl(x);
        if (lane < nw) smem[lane] = xi - x;
        if (lane == nw - 1) smem[32] = xi;
    }
    __syncthreads();
    T res = inc - v + smem[w];
    T tot = smem[32];
    __syncthreads();
    if (total) *total = tot;
    return res;
}

// ---------------- kernels --------------------------------------------------
__global__ void k_zero_deg() {
    int i = blockIdx.x * blockDim.x + threadIdx.x;
    if (i < MAX_ATOM) g_deg[i] = 0;
}

// Filter: per-tile kept count + run-aggregated degree histogram + keep-mask.
__global__ void k_filter(const int* __restrict__ src, const float* __restrict__ len,
                         int n_bond) {
    __shared__ int sm[33];
    int base = blockIdx.x * TILE + threadIdx.x * ITEMS;
    int curA = -1, curC = 0;
    unsigned byteFlags = 0;
    if (base + ITEMS <= n_bond) {
        float4 l0 = *(const float4*)(len + base);
        float4 l1 = *(const float4*)(len + base + 4);
        int4 s0 = *(const int4*)(src + base);
        int4 s1 = *(const int4*)(src + base + 4);
        float lv[8] = {l0.x, l0.y, l0.z, l0.w, l1.x, l1.y, l1.z, l1.w};
        int sv[8] = {s0.x, s0.y, s0.z, s0.w, s1.x, s1.y, s1.z, s1.w};
#pragma unroll
        for (int i = 0; i < 8; i++) {
            if (lv[i] <= CUTOFF) {
                byteFlags |= (1u << i);
                int a = sv[i];
                if (a == curA) curC++;
                else { if (curC) atomicAdd(&g_deg[curA], curC); curA = a; curC = 1; }
            }
        }
    } else {
        for (int i = 0; i < ITEMS; i++) {
            int b = base + i;
            if (b < n_bond && len[b] <= CUTOFF) {
                byteFlags |= (1u << i);
                int a = src[b];
                if (a == curA) curC++;
                else { if (curC) atomicAdd(&g_deg[curA], curC); curA = a; curC = 1; }
            }
        }
    }
    if (curC) atomicAdd(&g_deg[curA], curC);

    // Combine 8 lanes' bytes into one u64 mask word.
    unsigned long long word = (unsigned long long)byteFlags << ((threadIdx.x & 7) * 8);
    word |= __shfl_xor_sync(0xffffffffu, word, 1);
    word |= __shfl_xor_sync(0xffffffffu, word, 2);
    word |= __shfl_xor_sync(0xffffffffu, word, 4);
    if ((threadIdx.x & 7) == 0) g_mask[base >> 6] = word;

    int tot;
    blockExcl<int>(__popc(byteFlags), sm, &tot);
    if (threadIdx.x == 0) g_btCnt[blockIdx.x] = tot;
}

// Single block: scan bond-tile counts; also struct bounds from n_atoms.
__global__ void k_scan_bt(int nbt, const int* __restrict__ n_atoms, int n_struct) {
    __shared__ int sm[33];
    int carry = 0;
    for (int base = 0; base < nbt; base += blockDim.x) {
        int i = base + threadIdx.x;
        int v = (i < nbt) ? g_btCnt[i] : 0;
        int tot;
        int e = blockExcl<int>(v, sm, &tot);
        if (i < nbt) g_btOff[i] = carry + e;
        carry += tot;
    }
    if (threadIdx.x == 0) {
        g_M = carry;
        int ns = n_struct < 256 ? n_struct : 256;
        int acc = 0;
        for (int s = 0; s < ns; s++) { g_bound[s] = acc; acc += n_atoms[s]; }
        g_bound[ns] = acc;
        g_nAtom = acc;
    }
}

// Order-preserving scatter of kept bond ids (mask-driven, no len re-read).
__global__ void k_scatter(int n_bond) {
    __shared__ int sm[33];
    int base = blockIdx.x * TILE + threadIdx.x * ITEMS;
    unsigned byteFlags = 0;
    if (base < n_bond) {
        unsigned long long w = g_mask[base >> 6];
        byteFlags = (unsigned)(w >> (((base >> 3) & 7) * 8)) & 0xFFu;
    }
    int e = blockExcl<int>(__popc(byteFlags), sm, (int*)nullptr);
    int pos = g_btOff[blockIdx.x] + e;
#pragma unroll
    for (int i = 0; i < ITEMS; i++)
        if ((byteFlags >> i) & 1u) g_kept[pos++] = base + i;
}

// Per-atom-tile packed (deg, tri) sums.
__global__ void k_atile() {
    __shared__ unsigned long long sm[33];
    int nA = g_nAtom;
    int base = blockIdx.x * TILE + threadIdx.x * ITEMS;
    unsigned long long acc = 0;
#pragma unroll
    for (int i = 0; i < ITEMS; i++) {
        int a = base + i;
        int d = (a < nA) ? g_deg[a] : 0;
        acc += ((unsigned long long)(unsigned)(d * (d - 1)) << 32) | (unsigned)d;
    }
    unsigned long long tot;
    blockExcl<unsigned long long>(acc, sm, &tot);
    if (threadIdx.x == 0) g_atPack[blockIdx.x] = tot;
}

__global__ void k_scan_at() {
    __shared__ unsigned long long sm[33];
    int nA = g_nAtom;
    int nt = (nA + TILE - 1) / TILE;
    unsigned long long carry = 0;
    for (int base = 0; base < nt; base += blockDim.x) {
        int i = base + threadIdx.x;
        unsigned long long v = (i < nt) ? g_atPack[i] : 0ull;
        unsigned long long tot;
        unsigned long long e = blockExcl<unsigned long long>(v, sm, &tot);
        if (i < nt) g_atPackOff[i] = carry + e;
        carry += tot;
    }
    if (threadIdx.x == 0) g_T = (int)(carry >> 32);
}

// Per-atom CSR offsets + triple starts + n_triple_i section (float out).
__global__ void k_awrite(float* __restrict__ out, int out_size, int n_bond, int n_struct) {
    __shared__ unsigned long long sm[33];
    int nA = g_nAtom;
    int base = blockIdx.x * TILE + threadIdx.x * ITEMS;
    int dArr[ITEMS];
    unsigned long long acc = 0;
#pragma unroll
    for (int i = 0; i < ITEMS; i++) {
        int a = base + i;
        int d = (a < nA) ? g_deg[a] : 0;
        dArr[i] = d;
        acc += ((unsigned long long)(unsigned)(d * (d - 1)) << 32) | (unsigned)d;
    }
    unsigned long long e = blockExcl<unsigned long long>(acc, sm, (unsigned long long*)nullptr);
    unsigned long long run =
        ((blockIdx.x * TILE < nA) ? g_atPackOff[blockIdx.x] : 0ull) + e;
    int offTi = out_size - n_struct - nA;
#pragma unroll
    for (int i = 0; i < ITEMS; i++) {
        int a = base + i;
        if (a < nA) {
            int d = dArr[i];
            g_ab[a] = make_int2((int)(run & 0xffffffffull), d);
            g_triStart[a] = (int)(run >> 32);
            out[offTi + a] = (float)(d * (d - 1));
            run += ((unsigned long long)(unsigned)(d * (d - 1)) << 32) | (unsigned)d;
        }
    }
}

// n_triple_s per structure.
__global__ void k_struct(float* __restrict__ out, int out_size, int n_struct) {
    int s = blockIdx.x * blockDim.x + threadIdx.x;
    if (s < n_struct) {
        int nA = g_nAtom;
        int lo = g_bound[s], hi = g_bound[s + 1];
        int vlo = (lo >= nA) ? g_T : g_triStart[lo];
        int vhi = (hi >= nA) ? g_T : g_triStart[hi];
        out[out_size - n_struct + s] = (float)(vhi - vlo);
    }
}

// n_triple_ij per ORIGINAL bond (mask-driven, vectorized).
__global__ void k_tij(const int* __restrict__ src, int n_bond,
                      float* __restrict__ out, int out_size, int n_struct) {
    int base = (blockIdx.x * blockDim.x + threadIdx.x) * 8;
    if (base >= n_bond) return;
    unsigned long long w = g_mask[base >> 6];
    unsigned byteFlags = (unsigned)(w >> (((base >> 3) & 7) * 8)) & 0xFFu;
    float* o = out + (out_size - n_struct - g_nAtom - n_bond);
    if (base + 8 <= n_bond) {
        int4 s0 = *(const int4*)(src + base);
        int4 s1 = *(const int4*)(src + base + 4);
        int sv[8] = {s0.x, s0.y, s0.z, s0.w, s1.x, s1.y, s1.z, s1.w};
        float r[8];
#pragma unroll
        for (int i = 0; i < 8; i++)
            r[i] = ((byteFlags >> i) & 1u) ? (float)(g_deg[sv[i]] - 1) : 0.0f;
        // tij section base offset is even (2T) -> float2 stores are aligned.
        float2* o2 = (float2*)(o + base);
        o2[0] = make_float2(r[0], r[1]);
        o2[1] = make_float2(r[2], r[3]);
        o2[2] = make_float2(r[4], r[5]);
        o2[3] = make_float2(r[6], r[7]);
    } else {
        for (int i = 0; i < 8 && base + i < n_bond; i++)
            o[base + i] = ((byteFlags >> i) & 1u) ? (float)(g_deg[src[base + i]] - 1) : 0.0f;
    }
}

// Triple-major pair emission: PITEMS consecutive flat triples per thread,
// one binary search per thread, coalesced float4 stores.
__global__ void k_pairs(float* __restrict__ out) {
    int T = g_T;
    int nA = g_nAtom;
    int stride = gridDim.x * blockDim.x * PITEMS;
    for (int t0 = (blockIdx.x * blockDim.x + threadIdx.x) * PITEMS; t0 < T; t0 += stride) {
        // largest a with triStart[a] <= t0
        int lo = 0, hi = nA - 1;
        while (lo < hi) {
            int mid = (lo + hi + 1) >> 1;
            if (g_triStart[mid] <= t0) lo = mid; else hi = mid - 1;
        }
        int a = lo;
        int local = t0 - g_triStart[a];
        int2 ab = g_ab[a];
        int d = ab.y, tri = d * (d - 1);
        float buf[2 * PITEMS];
        int n = min(PITEMS, T - t0);
#pragma unroll
        for (int i = 0; i < PITEMS; i++) {
            if (i < n) {
                while (local >= tri) {
                    local -= tri;
                    a++;
                    ab = g_ab[a];
                    d = ab.y;
                    tri = d * (d - 1);
                }
                int j = local / (d - 1);
                int kp = local - j * (d - 1);
                int k = kp + (kp >= j);
                buf[2 * i] = (float)g_kept[ab.x + j];
                buf[2 * i + 1] = (float)g_kept[ab.x + k];
                local++;
            }
        }
        if (n == PITEMS) {
            float4* o4 = (float4*)(out + 2 * t0);  // t0 % 8 == 0 -> 64B aligned
            o4[0] = make_float4(buf[0], buf[1], buf[2], buf[3]);
            o4[1] = make_float4(buf[4], buf[5], buf[6], buf[7]);
            o4[2] = make_float4(buf[8], buf[9], buf[10], buf[11]);
            o4[3] = make_float4(buf[12], buf[13], buf[14], buf[15]);
        } else {
            for (int i = 0; i < n; i++) {
                out[2 * (t0 + i)] = buf[2 * i];
                out[2 * (t0 + i) + 1] = buf[2 * i + 1];
            }
        }
    }
}

// ---------------- launch ----------------------------------------------------
extern "C" void kernel_launch(void* const* d_in, const int* in_sizes, int n_in,
                              void* d_out, int out_size) {
    const int* src = (const int*)d_in[0];
    const float* len = (const float*)d_in[1];
    const int* n_atoms = (const int*)d_in[2];
    int n_bond = in_sizes[0];
    int n_struct = in_sizes[2];
    float* out = (float*)d_out;

    int nbt = (n_bond + TILE - 1) / TILE;
    int ntij = (n_bond + TPB * 8 - 1) / (TPB * 8);

    k_zero_deg<<<(MAX_ATOM + 255) / 256, 256>>>();
    k_filter<<<nbt, TPB>>>(src, len, n_bond);
    k_scan_bt<<<1, 1024>>>(nbt, n_atoms, n_struct);
    k_scatter<<<nbt, TPB>>>(n_bond);
    k_atile<<<MAX_ATILES, TPB>>>();
    k_scan_at<<<1, 1024>>>();
    k_awrite<<<MAX_ATILES, TPB>>>(out, out_size, n_bond, n_struct);
    k_struct<<<1, 256>>>(out, out_size, n_struct);
    k_tij<<<ntij, TPB>>>(src, n_bond, out, out_size, n_struct);
    k_pairs<<<PAIR_BLOCKS, TPB>>>(out);
}

// round 4
// speedup vs baseline: 1.6005x; 1.2410x over previous
#include <cuda_runtime.h>

#define TPB 512
#define ITEMS 4
#define TILE 2048                     // TPB * ITEMS
#define NBLK 296                      // 2 CTAs/SM on 148+ SMs, co-resident
#define MAX_BOND (1 << 22)
#define MAX_ATOM (1 << 20)
#define MAX_TILES (MAX_BOND / TILE)
#define MAX_ATILES (MAX_ATOM / TILE)
#define MAX_GROUPS (1 << 23)          // supports up to 64M triples
#define CUTOFF 0.8f

// ---------------- scratch (static device globals; no allocations) ----------
__device__ int g_deg[MAX_ATOM];
__device__ int2 g_ab[MAX_ATOM];       // {bondOff, deg}
__device__ int g_triStart[MAX_ATOM];
__device__ float g_keptF[MAX_BOND];   // kept bond ids, pre-converted to float
__device__ unsigned long long g_mask[MAX_BOND / 64];
__device__ int g_tileCnt[MAX_TILES];
__device__ int g_tileOff[MAX_TILES];
__device__ unsigned long long g_atPack[MAX_ATILES];
__device__ unsigned long long g_atPackOff[MAX_ATILES];
__device__ int g_lookup[MAX_GROUPS];  // group -> owning atom
__device__ int g_M, g_T, g_nAtom;
__device__ int g_bound[260];
__device__ volatile int g_barArrive;
__device__ volatile unsigned g_barGen;

// ---------------- helpers ---------------------------------------------------
__device__ __forceinline__ void gridBarrier() {
    __syncthreads();
    if (threadIdx.x == 0) {
        __threadfence();
        unsigned gen = g_barGen;
        if (atomicAdd((int*)&g_barArrive, 1) == NBLK - 1) {
            g_barArrive = 0;
            __threadfence();
            g_barGen = gen + 1;
        } else {
            while (g_barGen == gen) __nanosleep(64);
        }
        __threadfence();
    }
    __syncthreads();
}

template <typename T>
__device__ __forceinline__ T warpIncl(T v) {
#pragma unroll
    for (int d = 1; d < 32; d <<= 1) {
        T n = __shfl_up_sync(0xffffffffu, v, d);
        if ((threadIdx.x & 31) >= d) v += n;
    }
    return v;
}

// Block exclusive scan for 512 threads; smem >= 33 elems; loop-safe.
template <typename T>
__device__ __forceinline__ T blockExcl(T v, T* smem, T* total) {
    int lane = threadIdx.x & 31, w = threadIdx.x >> 5, nw = TPB >> 5;
    T inc = warpIncl(v);
    if (lane == 31) smem[w] = inc;
    __syncthreads();
    if (w == 0) {
        T x = (lane < nw) ? smem[lane] : (T)0;
        T xi = warpIncl(x);
        if (lane < nw) smem[lane] = xi - x;
        if (lane == nw - 1) smem[32] = xi;
    }
    __syncthreads();
    T res = inc - v + smem[w];
    T tot = smem[32];
    __syncthreads();
    if (total) *total = tot;
    return res;
}

// ---------------- the fused kernel ------------------------------------------
__global__ __launch_bounds__(TPB, 2) void fused(
    const int* __restrict__ src, const float* __restrict__ len,
    const int* __restrict__ n_atoms, int n_bond, int n_struct,
    float* __restrict__ out, int out_size) {
    __shared__ unsigned long long smLL[33];
    __shared__ int smStage[TILE];

    int tid = threadIdx.x;
    int gtid = blockIdx.x * TPB + tid;
    const int gsize = NBLK * TPB;
    int nTiles = (n_bond + TILE - 1) / TILE;

    // ---- P0: zero degrees; struct bounds ----
    for (int i = gtid; i < MAX_ATOM; i += gsize) g_deg[i] = 0;
    if (gtid == 0) {
        int ns = n_struct < 256 ? n_struct : 256;
        int acc = 0;
        for (int s = 0; s < ns; s++) { g_bound[s] = acc; acc += n_atoms[s]; }
        g_bound[ns] = acc;
        g_nAtom = acc;
    }
    gridBarrier();

    // ---- P1: filter (mask + per-tile counts + run-aggregated degrees) ----
    for (int tile = blockIdx.x; tile < nTiles; tile += NBLK) {
        int base = tile * TILE + tid * ITEMS;
        unsigned nib = 0;
        int curA = -1, curC = 0;
        if (base + ITEMS <= n_bond) {
            float4 l = *(const float4*)(len + base);
            int4 s = *(const int4*)(src + base);
            float lv[4] = {l.x, l.y, l.z, l.w};
            int sv[4] = {s.x, s.y, s.z, s.w};
#pragma unroll
            for (int i = 0; i < 4; i++) {
                if (lv[i] <= CUTOFF) {
                    nib |= 1u << i;
                    if (sv[i] == curA) curC++;
                    else { if (curC) atomicAdd(&g_deg[curA], curC); curA = sv[i]; curC = 1; }
                }
            }
        } else {
            for (int i = 0; i < 4; i++) {
                int b = base + i;
                if (b < n_bond && len[b] <= CUTOFF) {
                    nib |= 1u << i;
                    int a = src[b];
                    if (a == curA) curC++;
                    else { if (curC) atomicAdd(&g_deg[curA], curC); curA = a; curC = 1; }
                }
            }
        }
        if (curC) atomicAdd(&g_deg[curA], curC);
        unsigned long long word = (unsigned long long)nib << ((tid & 15) * 4);
        word |= __shfl_xor_sync(0xffffffffu, word, 1);
        word |= __shfl_xor_sync(0xffffffffu, word, 2);
        word |= __shfl_xor_sync(0xffffffffu, word, 4);
        word |= __shfl_xor_sync(0xffffffffu, word, 8);
        if ((tid & 15) == 0) g_mask[tile * 32 + (tid >> 4)] = word;
        unsigned long long tot;
        blockExcl<unsigned long long>((unsigned long long)__popc(nib), smLL, &tot);
        if (tid == 0) g_tileCnt[tile] = (int)tot;
    }
    gridBarrier();

    // ---- P2: block 0 scans tile counts ----
    if (blockIdx.x == 0) {
        int carry = 0;
        for (int b0 = 0; b0 < nTiles; b0 += TPB) {
            int i = b0 + tid;
            unsigned long long v = (i < nTiles) ? (unsigned long long)g_tileCnt[i] : 0ull;
            unsigned long long tot;
            unsigned long long e = blockExcl<unsigned long long>(v, smLL, &tot);
            if (i < nTiles) g_tileOff[i] = carry + (int)e;
            carry += (int)tot;
        }
        if (tid == 0) g_M = carry;
    }
    gridBarrier();

    int nA = g_nAtom;
    int nAT = (nA + TILE - 1) / TILE;

    // ---- P3a: scatter kept bond ids as floats (smem-staged, coalesced) ----
    for (int tile = blockIdx.x; tile < nTiles; tile += NBLK) {
        int base = tile * TILE + tid * ITEMS;
        unsigned nib = 0;
        if (base < n_bond) {
            unsigned long long w = g_mask[tile * 32 + (tid >> 4)];
            nib = (unsigned)(w >> ((tid & 15) * 4)) & 0xFu;
        }
        unsigned long long totL;
        int e = (int)blockExcl<unsigned long long>((unsigned long long)__popc(nib), smLL, &totL);
#pragma unroll
        for (int i = 0; i < 4; i++)
            if ((nib >> i) & 1u) smStage[e++] = base + i;
        __syncthreads();
        int tot = (int)totL;
        int off = g_tileOff[tile];
        for (int i = tid; i < tot; i += TPB) g_keptF[off + i] = (float)smStage[i];
        __syncthreads();
    }

    // ---- P3b: n_triple_ij section ----
    int offTij = out_size - n_struct - nA - n_bond;
    int nBG = (n_bond + 3) >> 2;
    for (int q = gtid; q < nBG; q += gsize) {
        int b0 = q * 4;
        unsigned long long w = g_mask[b0 >> 6];
        unsigned nib = (unsigned)(w >> (b0 & 63)) & 0xFu;
        if (b0 + 4 <= n_bond) {
            int4 s = *(const int4*)(src + b0);
            float r0 = (nib & 1u) ? (float)(g_deg[s.x] - 1) : 0.0f;
            float r1 = (nib & 2u) ? (float)(g_deg[s.y] - 1) : 0.0f;
            float r2 = (nib & 4u) ? (float)(g_deg[s.z] - 1) : 0.0f;
            float r3 = (nib & 8u) ? (float)(g_deg[s.w] - 1) : 0.0f;
            float2* o2 = (float2*)(out + offTij + b0);  // 2T even -> 8B aligned
            o2[0] = make_float2(r0, r1);
            o2[1] = make_float2(r2, r3);
        } else {
            for (int i = 0; b0 + i < n_bond; i++)
                out[offTij + b0 + i] =
                    ((nib >> i) & 1u) ? (float)(g_deg[src[b0 + i]] - 1) : 0.0f;
        }
    }

    // ---- P3c: per-atom-tile packed (tri<<32 | deg) sums ----
    for (int t = blockIdx.x; t < nAT; t += NBLK) {
        int base = t * TILE + tid * ITEMS;
        unsigned long long acc = 0;
#pragma unroll
        for (int i = 0; i < 4; i++) {
            int a = base + i;
            int d = (a < nA) ? g_deg[a] : 0;
            acc += ((unsigned long long)(unsigned)(d * (d - 1)) << 32) | (unsigned)d;
        }
        unsigned long long tot;
        blockExcl<unsigned long long>(acc, smLL, &tot);
        if (tid == 0) g_atPack[t] = tot;
    }
    gridBarrier();

    // ---- P4: block 0 scans atom-tile sums ----
    if (blockIdx.x == 0) {
        unsigned long long carry = 0;
        for (int b0 = 0; b0 < nAT; b0 += TPB) {
            int i = b0 + tid;
            unsigned long long v = (i < nAT) ? g_atPack[i] : 0ull;
            unsigned long long tot;
            unsigned long long e = blockExcl<unsigned long long>(v, smLL, &tot);
            if (i < nAT) g_atPackOff[i] = carry + e;
            carry += tot;
        }
        if (tid == 0) g_T = (int)(carry >> 32);
    }
    gridBarrier();

    // ---- P5: per-atom CSR offsets, triStart, n_triple_i section ----
    int offTi = out_size - n_struct - nA;
    for (int t = blockIdx.x; t < nAT; t += NBLK) {
        int base = t * TILE + tid * ITEMS;
        int dA[4];
        unsigned long long acc = 0;
#pragma unroll
        for (int i = 0; i < 4; i++) {
            int a = base + i;
            int d = (a < nA) ? g_deg[a] : 0;
            dA[i] = d;
            acc += ((unsigned long long)(unsigned)(d * (d - 1)) << 32) | (unsigned)d;
        }
        unsigned long long e =
            blockExcl<unsigned long long>(acc, smLL, (unsigned long long*)0);
        unsigned long long run = g_atPackOff[t] + e;
#pragma unroll
        for (int i = 0; i < 4; i++) {
            int a = base + i;
            if (a < nA) {
                int d = dA[i];
                g_ab[a] = make_int2((int)(run & 0xffffffffull), d);
                g_triStart[a] = (int)(run >> 32);
                out[offTi + a] = (float)(d * (d - 1));
                run += ((unsigned long long)(unsigned)(d * (d - 1)) << 32) | (unsigned)d;
            }
        }
    }
    gridBarrier();

    // ---- P6: group->atom lookup fill + n_triple_s section ----
    for (int a = gtid; a < nA; a += gsize) {
        int ts = g_triStart[a];
        int d = g_ab[a].y;
        int tri = d * (d - 1);
        int g0 = (ts + 7) >> 3, g1 = (ts + tri + 7) >> 3;
        for (int g = g0; g < g1; g++) g_lookup[g] = a;
    }
    if (gtid < n_struct) {
        int T = g_T;
        int lo = g_bound[gtid], hi = g_bound[gtid + 1];
        int vlo = (lo >= nA) ? T : g_triStart[lo];
        int vhi = (hi >= nA) ? T : g_triStart[hi];
        out[out_size - n_struct + gtid] = (float)(vhi - vlo);
    }
    gridBarrier();

    // ---- P7: pair emission, 8 triples/thread, no division in inner loop ----
    int T = g_T;
    int nG = (T + 7) >> 3;
    for (int g = gtid; g < nG; g += gsize) {
        int t0 = g << 3;
        int a = g_lookup[g];
        int local = t0 - g_triStart[a];
        int2 ab = g_ab[a];
        int d = ab.y, dm1 = d - 1;
        int j = local / dm1;
        int kp = local - j * dm1;
        float bj = g_keptF[ab.x + j];
        float buf[16];
        int n = min(8, T - t0);
#pragma unroll
        for (int i = 0; i < 8; i++) {
            if (i < n) {
                int k = kp + (kp >= j);
                buf[2 * i] = bj;
                buf[2 * i + 1] = g_keptF[ab.x + k];
                if (i + 1 < n) {
                    if (++kp == dm1) {
                        kp = 0;
                        if (++j == d) {
                            do { a++; ab = g_ab[a]; d = ab.y; } while (d < 2);
                            dm1 = d - 1;
                            j = 0;
                        }
                        bj = g_keptF[ab.x + j];
                    }
                }
            }
        }
        if (n == 8) {
            float4* o4 = (float4*)(out + 2 * t0);  // 16*g floats -> 64B aligned
            o4[0] = make_float4(buf[0], buf[1], buf[2], buf[3]);
            o4[1] = make_float4(buf[4], buf[5], buf[6], buf[7]);
            o4[2] = make_float4(buf[8], buf[9], buf[10], buf[11]);
            o4[3] = make_float4(buf[12], buf[13], buf[14], buf[15]);
        } else {
            for (int i = 0; i < n; i++) {
                out[2 * (t0 + i)] = buf[2 * i];
                out[2 * (t0 + i) + 1] = buf[2 * i + 1];
            }
        }
    }
}

// ---------------- launch ----------------------------------------------------
extern "C" void kernel_launch(void* const* d_in, const int* in_sizes, int n_in,
                              void* d_out, int out_size) {
    const int* src = (const int*)d_in[0];
    const float* len = (const float*)d_in[1];
    const int* n_atoms = (const int*)d_in[2];
    int n_bond = in_sizes[0];
    int n_struct = in_sizes[2];
    fused<<<NBLK, TPB>>>(src, len, n_atoms, n_bond, n_struct, (float*)d_out,
                         out_size);
}

// round 5
// speedup vs baseline: 1.6168x; 1.0102x over previous
#include <cuda_runtime.h>

#define TPB 512
#define ITEMS 4
#define TILE 2048                     // TPB * ITEMS
#define NBLK 296                      // 2 CTAs/SM, co-resident
#define MAX_BOND (1 << 22)
#define MAX_ATOM (1 << 20)
#define MAX_TILES (MAX_BOND / TILE)
#define MAX_ATILES (MAX_ATOM / TILE)
#define MAX_GROUPS (1 << 22)          // supports up to 33.5M triples
#define CUTOFF 0.8f

// ---------------- scratch (static device globals; no allocations) ----------
__device__ int g_deg[MAX_ATOM];
__device__ int2 g_ab[MAX_ATOM];       // {bondOff, deg}
__device__ int g_triStart[MAX_ATOM];
__device__ float g_keptF[MAX_BOND];   // kept bond ids, pre-converted to float
__device__ unsigned long long g_mask[MAX_BOND / 64];
__device__ int g_tileCnt[MAX_TILES];
__device__ int g_tileOff[MAX_TILES];
__device__ unsigned long long g_atPack[MAX_ATILES];
__device__ unsigned long long g_atPackOff[MAX_ATILES];
__device__ int4 g_grp[MAX_GROUPS];    // per-8-triple group: {bondOff, triStart, deg, atom}
__device__ int g_M, g_T, g_nAtom;
__device__ int g_bound[260];
__device__ volatile int g_barArrive;
__device__ volatile unsigned g_barGen;

// ---------------- helpers ---------------------------------------------------
__device__ __forceinline__ void gridBarrier() {
    __syncthreads();
    if (threadIdx.x == 0) {
        __threadfence();
        unsigned gen = g_barGen;
        if (atomicAdd((int*)&g_barArrive, 1) == NBLK - 1) {
            g_barArrive = 0;
            __threadfence();
            g_barGen = gen + 1;
        } else {
            while (g_barGen == gen) __nanosleep(64);
        }
        __threadfence();
    }
    __syncthreads();
}

template <typename T>
__device__ __forceinline__ T warpIncl(T v) {
#pragma unroll
    for (int d = 1; d < 32; d <<= 1) {
        T n = __shfl_up_sync(0xffffffffu, v, d);
        if ((threadIdx.x & 31) >= d) v += n;
    }
    return v;
}

template <typename T>
__device__ __forceinline__ T blockExcl(T v, T* smem, T* total) {
    int lane = threadIdx.x & 31, w = threadIdx.x >> 5, nw = TPB >> 5;
    T inc = warpIncl(v);
    if (lane == 31) smem[w] = inc;
    __syncthreads();
    if (w == 0) {
        T x = (lane < nw) ? smem[lane] : (T)0;
        T xi = warpIncl(x);
        if (lane < nw) smem[lane] = xi - x;
        if (lane == nw - 1) smem[32] = xi;
    }
    __syncthreads();
    T res = inc - v + smem[w];
    T tot = smem[32];
    __syncthreads();
    if (total) *total = tot;
    return res;
}

// ---------------- the fused kernel ------------------------------------------
__global__ __launch_bounds__(TPB, 2) void fused(
    const int* __restrict__ src, const float* __restrict__ len,
    const int* __restrict__ n_atoms, int n_bond, int n_struct,
    float* __restrict__ out, int out_size) {
    __shared__ unsigned long long smLL[33];
    __shared__ int smStage[TILE];

    int tid = threadIdx.x;
    int gtid = blockIdx.x * TPB + tid;
    const int gsize = NBLK * TPB;
    int nTiles = (n_bond + TILE - 1) / TILE;

    // ---- P0: zero degrees (only [0,nA)); struct bounds ----
    int nA = 0;
    for (int s = 0; s < n_struct; s++) nA += n_atoms[s];
    for (int i = gtid; i < nA; i += gsize) g_deg[i] = 0;
    if (gtid == 0) {
        int ns = n_struct < 256 ? n_struct : 256;
        int acc = 0;
        for (int s = 0; s < ns; s++) { g_bound[s] = acc; acc += n_atoms[s]; }
        g_bound[ns] = acc;
        g_nAtom = acc;
    }
    gridBarrier();

    // ---- P1: filter (mask + per-tile counts + run-aggregated degrees) ----
    for (int tile = blockIdx.x; tile < nTiles; tile += NBLK) {
        int base = tile * TILE + tid * ITEMS;
        unsigned nib = 0;
        int curA = -1, curC = 0;
        if (base + ITEMS <= n_bond) {
            float4 l = *(const float4*)(len + base);
            int4 s = *(const int4*)(src + base);
            float lv[4] = {l.x, l.y, l.z, l.w};
            int sv[4] = {s.x, s.y, s.z, s.w};
#pragma unroll
            for (int i = 0; i < 4; i++) {
                if (lv[i] <= CUTOFF) {
                    nib |= 1u << i;
                    if (sv[i] == curA) curC++;
                    else { if (curC) atomicAdd(&g_deg[curA], curC); curA = sv[i]; curC = 1; }
                }
            }
        } else {
            for (int i = 0; i < 4; i++) {
                int b = base + i;
                if (b < n_bond && len[b] <= CUTOFF) {
                    nib |= 1u << i;
                    int a = src[b];
                    if (a == curA) curC++;
                    else { if (curC) atomicAdd(&g_deg[curA], curC); curA = a; curC = 1; }
                }
            }
        }
        if (curC) atomicAdd(&g_deg[curA], curC);
        unsigned long long word = (unsigned long long)nib << ((tid & 15) * 4);
        word |= __shfl_xor_sync(0xffffffffu, word, 1);
        word |= __shfl_xor_sync(0xffffffffu, word, 2);
        word |= __shfl_xor_sync(0xffffffffu, word, 4);
        word |= __shfl_xor_sync(0xffffffffu, word, 8);
        if ((tid & 15) == 0) g_mask[tile * 32 + (tid >> 4)] = word;
        unsigned long long tot;
        blockExcl<unsigned long long>((unsigned long long)__popc(nib), smLL, &tot);
        if (tid == 0) g_tileCnt[tile] = (int)tot;
    }
    gridBarrier();

    // ---- P2: block 0 scans tile counts ----
    if (blockIdx.x == 0) {
        int carry = 0;
        for (int b0 = 0; b0 < nTiles; b0 += TPB) {
            int i = b0 + tid;
            unsigned long long v = (i < nTiles) ? (unsigned long long)g_tileCnt[i] : 0ull;
            unsigned long long tot;
            unsigned long long e = blockExcl<unsigned long long>(v, smLL, &tot);
            if (i < nTiles) g_tileOff[i] = carry + (int)e;
            carry += (int)tot;
        }
        if (tid == 0) g_M = carry;
    }
    gridBarrier();

    int nAT = (nA + TILE - 1) / TILE;

    // ---- P3a: scatter kept bond ids as floats (smem-staged, coalesced) ----
    for (int tile = blockIdx.x; tile < nTiles; tile += NBLK) {
        int base = tile * TILE + tid * ITEMS;
        unsigned nib = 0;
        if (base < n_bond) {
            unsigned long long w = g_mask[tile * 32 + (tid >> 4)];
            nib = (unsigned)(w >> ((tid & 15) * 4)) & 0xFu;
        }
        unsigned long long totL;
        int e = (int)blockExcl<unsigned long long>((unsigned long long)__popc(nib), smLL, &totL);
#pragma unroll
        for (int i = 0; i < 4; i++)
            if ((nib >> i) & 1u) smStage[e++] = base + i;
        __syncthreads();
        int tot = (int)totL;
        int off = g_tileOff[tile];
        for (int i = tid; i < tot; i += TPB) g_keptF[off + i] = (float)smStage[i];
        __syncthreads();
    }

    // ---- P3b: n_triple_ij section ----
    int offTij = out_size - n_struct - nA - n_bond;
    int nBG = (n_bond + 3) >> 2;
    for (int q = gtid; q < nBG; q += gsize) {
        int b0 = q * 4;
        unsigned long long w = g_mask[b0 >> 6];
        unsigned nib = (unsigned)(w >> (b0 & 63)) & 0xFu;
        if (b0 + 4 <= n_bond) {
            int4 s = *(const int4*)(src + b0);
            float4 r;
            r.x = (nib & 1u) ? (float)(g_deg[s.x] - 1) : 0.0f;
            r.y = (nib & 2u) ? (float)(g_deg[s.y] - 1) : 0.0f;
            r.z = (nib & 4u) ? (float)(g_deg[s.z] - 1) : 0.0f;
            r.w = (nib & 8u) ? (float)(g_deg[s.w] - 1) : 0.0f;
            // 2T even, b0 multiple of 4 -> 16B aligned
            __stcs((float4*)(out + offTij + b0), r);
        } else {
            for (int i = 0; b0 + i < n_bond; i++)
                out[offTij + b0 + i] =
                    ((nib >> i) & 1u) ? (float)(g_deg[src[b0 + i]] - 1) : 0.0f;
        }
    }

    // ---- P3c: per-atom-tile packed (tri<<32 | deg) sums ----
    for (int t = blockIdx.x; t < nAT; t += NBLK) {
        int base = t * TILE + tid * ITEMS;
        unsigned long long acc = 0;
#pragma unroll
        for (int i = 0; i < 4; i++) {
            int a = base + i;
            int d = (a < nA) ? g_deg[a] : 0;
            acc += ((unsigned long long)(unsigned)(d * (d - 1)) << 32) | (unsigned)d;
        }
        unsigned long long tot;
        blockExcl<unsigned long long>(acc, smLL, &tot);
        if (tid == 0) g_atPack[t] = tot;
    }
    gridBarrier();

    // ---- P4: block 0 scans atom-tile sums ----
    if (blockIdx.x == 0) {
        unsigned long long carry = 0;
        for (int b0 = 0; b0 < nAT; b0 += TPB) {
            int i = b0 + tid;
            unsigned long long v = (i < nAT) ? g_atPack[i] : 0ull;
            unsigned long long tot;
            unsigned long long e = blockExcl<unsigned long long>(v, smLL, &tot);
            if (i < nAT) g_atPackOff[i] = carry + e;
            carry += tot;
        }
        if (tid == 0) g_T = (int)(carry >> 32);
    }
    gridBarrier();

    // ---- P5: per-atom CSR offsets, triStart, n_triple_i section ----
    int offTi = out_size - n_struct - nA;
    for (int t = blockIdx.x; t < nAT; t += NBLK) {
        int base = t * TILE + tid * ITEMS;
        int dA[4];
        unsigned long long acc = 0;
#pragma unroll
        for (int i = 0; i < 4; i++) {
            int a = base + i;
            int d = (a < nA) ? g_deg[a] : 0;
            dA[i] = d;
            acc += ((unsigned long long)(unsigned)(d * (d - 1)) << 32) | (unsigned)d;
        }
        unsigned long long e =
            blockExcl<unsigned long long>(acc, smLL, (unsigned long long*)0);
        unsigned long long run = g_atPackOff[t] + e;
#pragma unroll
        for (int i = 0; i < 4; i++) {
            int a = base + i;
            if (a < nA) {
                int d = dA[i];
                g_ab[a] = make_int2((int)(run & 0xffffffffull), d);
                g_triStart[a] = (int)(run >> 32);
                out[offTi + a] = (float)(d * (d - 1));
                run += ((unsigned long long)(unsigned)(d * (d - 1)) << 32) | (unsigned)d;
            }
        }
    }
    gridBarrier();

    // ---- P6: group record fill + n_triple_s section ----
    for (int a = gtid; a < nA; a += gsize) {
        int ts = g_triStart[a];
        int2 ab = g_ab[a];
        int d = ab.y;
        int tri = d * (d - 1);
        if (tri == 0) continue;
        int g0 = (ts + 7) >> 3, g1 = (ts + tri + 7) >> 3;
        int4 rec = make_int4(ab.x, ts, d, a);
        for (int g = g0; g < g1; g++) __stcs(&g_grp[g], rec);
    }
    if (gtid < n_struct) {
        int T = g_T;
        int lo = g_bound[gtid], hi = g_bound[gtid + 1];
        int vlo = (lo >= nA) ? T : g_triStart[lo];
        int vhi = (hi >= nA) ? T : g_triStart[hi];
        out[out_size - n_struct + gtid] = (float)(vhi - vlo);
    }
    gridBarrier();

    // ---- P7: pair emission. Per 8-triple group: one coalesced record load,
    //      pure-ALU index walk, then 16 independent gathers + 4 stcs stores.
    int T = g_T;
    int nG = (T + 7) >> 3;
    for (int g = gtid; g < nG; g += gsize) {
        int t0 = g << 3;
        int4 rec = __ldcs(&g_grp[g]);
        int off = rec.x, d = rec.z, a = rec.w;
        int dm1 = d - 1;
        int local = t0 - rec.y;
        int j = local / dm1;
        int kp = local - j * dm1;
        int idxj[8], idxk[8];
        int n = min(8, T - t0);
#pragma unroll
        for (int i = 0; i < 8; i++) {
            if (i < n) {
                idxj[i] = off + j;
                idxk[i] = off + kp + (kp >= j);
                if (i + 1 < n) {
                    if (++kp == dm1) {
                        kp = 0;
                        if (++j == d) {
                            int2 ab;
                            do { a++; ab = g_ab[a]; } while (ab.y < 2);
                            off = ab.x; d = ab.y; dm1 = d - 1; j = 0;
                        }
                    }
                }
            }
        }
        if (n == 8) {
            float4 o0, o1, o2, o3;
            o0.x = g_keptF[idxj[0]]; o0.y = g_keptF[idxk[0]];
            o0.z = g_keptF[idxj[1]]; o0.w = g_keptF[idxk[1]];
            o1.x = g_keptF[idxj[2]]; o1.y = g_keptF[idxk[2]];
            o1.z = g_keptF[idxj[3]]; o1.w = g_keptF[idxk[3]];
            o2.x = g_keptF[idxj[4]]; o2.y = g_keptF[idxk[4]];
            o2.z = g_keptF[idxj[5]]; o2.w = g_keptF[idxk[5]];
            o3.x = g_keptF[idxj[6]]; o3.y = g_keptF[idxk[6]];
            o3.z = g_keptF[idxj[7]]; o3.w = g_keptF[idxk[7]];
            float4* o4 = (float4*)(out + 2 * t0);  // 16*g floats -> 64B aligned
            __stcs(o4 + 0, o0);
            __stcs(o4 + 1, o1);
            __stcs(o4 + 2, o2);
            __stcs(o4 + 3, o3);
        } else {
            for (int i = 0; i < n; i++) {
                out[2 * (t0 + i)] = g_keptF[idxj[i]];
                out[2 * (t0 + i) + 1] = g_keptF[idxk[i]];
            }
        }
    }
}

// ---------------- launch ----------------------------------------------------
extern "C" void kernel_launch(void* const* d_in, const int* in_sizes, int n_in,
                              void* d_out, int out_size) {
    const int* src = (const int*)d_in[0];
    const float* len = (const float*)d_in[1];
    const int* n_atoms = (const int*)d_in[2];
    int n_bond = in_sizes[0];
    int n_struct = in_sizes[2];
    fused<<<NBLK, TPB>>>(src, len, n_atoms, n_bond, n_struct, (float*)d_out,
                         out_size);
}